// round 2
// baseline (speedup 1.0000x reference)
#include <cuda_runtime.h>
#include <cstdint>
#include <cstddef>

// Problem dims (fixed by the dataset)
#define BD 2048   // batch
#define MD 512    // measurements
#define AD 2048   // ambient
#define SD 6144   // S = A*3
#define NB 64     // Cholesky block

// ---------------- device scratch (no allocations allowed) ----------------
__device__ float g_G[AD * AD];        // Gram matrix / Cholesky workspace
__device__ float g_linv[NB * NB];     // inv of diagonal Cholesky block
__device__ float g_dU[AD];            // 1 / u_kk
__device__ float g_x0[BD * AD];       // y @ a
__device__ float g_xh[BD * AD];       // x_hat
__device__ float g_u[BD * SD];        // ADMM u
__device__ float g_w[BD * SD];        // w = z - u
__device__ unsigned g_mm[2];          // [0]=min key, [1]=max key (ordered-uint space)

// ---------------- float <-> order-preserving unsigned ----------------
__device__ __forceinline__ unsigned f2o(float f) {
    unsigned b = __float_as_uint(f);
    return (b & 0x80000000u) ? ~b : (b | 0x80000000u);
}
__device__ __forceinline__ float o2f(unsigned u) {
    unsigned b = (u & 0x80000000u) ? (u ^ 0x80000000u) : ~u;
    return __uint_as_float(b);
}

__global__ void mm_init_k() {
    g_mm[0] = 0xFFFFFFFFu;
    g_mm[1] = 0u;
}

__global__ void mm_reduce_k(const float* __restrict__ x, int n) {
    unsigned mn = 0xFFFFFFFFu, mx = 0u;
    for (int i = blockIdx.x * blockDim.x + threadIdx.x; i < n; i += gridDim.x * blockDim.x) {
        unsigned o = f2o(x[i]);
        mn = min(mn, o);
        mx = max(mx, o);
    }
    __shared__ unsigned smn[256], smx[256];
    smn[threadIdx.x] = mn;
    smx[threadIdx.x] = mx;
    __syncthreads();
    for (int s = 128; s > 0; s >>= 1) {
        if (threadIdx.x < s) {
            smn[threadIdx.x] = min(smn[threadIdx.x], smn[threadIdx.x + s]);
            smx[threadIdx.x] = max(smx[threadIdx.x], smx[threadIdx.x + s]);
        }
        __syncthreads();
    }
    if (threadIdx.x == 0) {
        atomicMin(&g_mm[0], smn[0]);
        atomicMax(&g_mm[1], smx[0]);
    }
}

// ---------------- iteration-1 x_hat = dU * x0 ----------------
__global__ void xhat1_k(const float* __restrict__ x0, const float* __restrict__ dU,
                        float* __restrict__ xh) {
    int i = blockIdx.x * blockDim.x + threadIdx.x;
    xh[i] = dU[i & (AD - 1)] * x0[i];
}

// ---------------- blocked Cholesky: diagonal block + inv(L11) ----------------
// One block of 64 threads. Factorizes 64x64 block in shared (lower), writes
// dU[k] = 1/l_kk^2, and writes Linv = inv(L11) row-major to g_linv.
__global__ void chol_diag_k(float* __restrict__ G, float* __restrict__ linv,
                            float* __restrict__ dU, int k0) {
    __shared__ float s[NB][NB + 1];
    __shared__ float xs[NB][NB + 1];
    int tid = threadIdx.x;  // 0..63

    for (int j = 0; j < NB; j++)
        s[tid][j] = G[(size_t)(k0 + tid) * AD + k0 + j];
    __syncthreads();

    for (int j = 0; j < NB; j++) {
        float ajj = s[j][j];
        __syncthreads();  // everyone read ajj before thread j overwrites it
        float d = sqrtf(ajj);
        if (tid == j) {
            s[j][j] = d;
            dU[k0 + j] = 1.0f / (d * d);
        }
        if (tid > j) s[tid][j] /= d;
        __syncthreads();
        if (tid > j) {
            float lj = s[tid][j];
            for (int p = j + 1; p <= tid; p++) s[tid][p] -= lj * s[p][j];
        }
        __syncthreads();
    }

    // inv(L11): thread = column c, forward substitution
    int c = tid;
    for (int r = 0; r < c; r++) xs[r][c] = 0.0f;
    xs[c][c] = 1.0f / s[c][c];
    for (int r = c + 1; r < NB; r++) {
        float acc = 0.0f;
        for (int p = c; p < r; p++) acc += s[r][p] * xs[p][c];
        xs[r][c] = -acc / s[r][r];
    }
    // linv[j*NB + p] = Linv[j][p]
    for (int j = 0; j < NB; j++) linv[j * NB + c] = xs[j][c];
}

// ---------------- panel: L21 = A21 * Linv^T, in place in G ----------------
// Each block: 32 rows. Loads its rows + Linv into shared first -> safe in-place.
__global__ void panel_k(float* __restrict__ G, const float* __restrict__ linv, int k0) {
    __shared__ float li[NB][NB + 1];
    __shared__ float ar[32][NB];
    int tid = threadIdx.x;  // 256
    for (int i = tid; i < NB * NB; i += 256) li[i >> 6][i & 63] = linv[i];
    int row0 = k0 + NB + blockIdx.x * 32;
    for (int i = tid; i < 32 * NB; i += 256) {
        int r = i >> 6, p = i & 63;
        ar[r][p] = G[(size_t)(row0 + r) * AD + k0 + p];
    }
    __syncthreads();
    int j = tid & 63;
    int rb = tid >> 6;  // 0..3
    for (int r = rb; r < 32; r += 4) {
        float acc = 0.0f;
#pragma unroll
        for (int p = 0; p < NB; p++) acc += ar[r][p] * li[j][p];
        G[(size_t)(row0 + r) * AD + k0 + j] = acc;
    }
}

// ---------------- generic tiled GEMM with fused epilogues ----------------
// TA: 0 -> A is MxK row-major (A[m*lda+k]);  1 -> A is KxM (A[k*lda+m])
// TB: 0 -> B is KxN row-major (B[k*ldb+n]);  1 -> B is NxK (B[n*ldb+k])
enum { EP_STORE = 0, EP_ADD, EP_SUB, EP_XHAT, EP_XHAT_CLIP, EP_ADMM, EP_ADMM_U0 };

template <int TA, int TB, int EPI, bool GUARD>
__global__ __launch_bounds__(256) void gemm_k(
    const float* __restrict__ A, const float* __restrict__ B, float* __restrict__ C,
    int M, int N, int K, int lda, int ldb, int ldc,
    const float* __restrict__ x0, const float* __restrict__ dU,
    float* __restrict__ ubuf, float* __restrict__ wbuf) {
    __shared__ float As[16][128];
    __shared__ float Bs[16][128];
    int tid = threadIdx.x;
    int bm0 = blockIdx.y * 128;
    int bn0 = blockIdx.x * 128;
    int tx = tid & 15, ty = tid >> 4;

    float acc[8][8];
#pragma unroll
    for (int i = 0; i < 8; i++)
#pragma unroll
        for (int j = 0; j < 8; j++) acc[i][j] = 0.0f;

    for (int k0 = 0; k0 < K; k0 += 16) {
        // ---- load A tile ----
        if (TA == 0) {
#pragma unroll
            for (int L = 0; L < 2; L++) {
                int idx = tid + L * 256;
                int r = idx >> 2;
                int fk = (idx & 3) << 2;
                float4 v = make_float4(0.f, 0.f, 0.f, 0.f);
                if (!GUARD || (bm0 + r) < M)
                    v = *(const float4*)(A + (size_t)(bm0 + r) * lda + k0 + fk);
                As[fk + 0][r] = v.x;
                As[fk + 1][r] = v.y;
                As[fk + 2][r] = v.z;
                As[fk + 3][r] = v.w;
            }
        } else {
#pragma unroll
            for (int L = 0; L < 2; L++) {
                int idx = tid + L * 256;
                int k = idx >> 5;
                int fm = (idx & 31) << 2;
                float4 v = make_float4(0.f, 0.f, 0.f, 0.f);
                if (!GUARD || (bm0 + fm) < M)
                    v = *(const float4*)(A + (size_t)(k0 + k) * lda + bm0 + fm);
                *(float4*)&As[k][fm] = v;
            }
        }
        // ---- load B tile ----
        if (TB == 0) {
#pragma unroll
            for (int L = 0; L < 2; L++) {
                int idx = tid + L * 256;
                int k = idx >> 5;
                int fn = (idx & 31) << 2;
                float4 v = make_float4(0.f, 0.f, 0.f, 0.f);
                if (!GUARD || (bn0 + fn) < N)
                    v = *(const float4*)(B + (size_t)(k0 + k) * ldb + bn0 + fn);
                *(float4*)&Bs[k][fn] = v;
            }
        } else {
#pragma unroll
            for (int L = 0; L < 2; L++) {
                int idx = tid + L * 256;
                int r = idx >> 2;
                int fk = (idx & 3) << 2;
                float4 v = make_float4(0.f, 0.f, 0.f, 0.f);
                if (!GUARD || (bn0 + r) < N)
                    v = *(const float4*)(B + (size_t)(bn0 + r) * ldb + k0 + fk);
                Bs[fk + 0][r] = v.x;
                Bs[fk + 1][r] = v.y;
                Bs[fk + 2][r] = v.z;
                Bs[fk + 3][r] = v.w;
            }
        }
        __syncthreads();
#pragma unroll
        for (int k = 0; k < 16; k++) {
            float arf[8], brf[8];
#pragma unroll
            for (int i = 0; i < 8; i++) arf[i] = As[k][ty * 8 + i];
#pragma unroll
            for (int j = 0; j < 8; j++) brf[j] = Bs[k][tx * 8 + j];
#pragma unroll
            for (int i = 0; i < 8; i++)
#pragma unroll
                for (int j = 0; j < 8; j++) acc[i][j] += arf[i] * brf[j];
        }
        __syncthreads();
    }

    // ---- epilogue ----
    float mnv = 0.f, mxv = 0.f;
    if (EPI == EP_XHAT_CLIP) {
        mnv = o2f(g_mm[0]);
        mxv = o2f(g_mm[1]);
    }
#pragma unroll
    for (int i = 0; i < 8; i++) {
        int row = bm0 + ty * 8 + i;
        if (GUARD && row >= M) continue;
#pragma unroll
        for (int j = 0; j < 8; j++) {
            int col = bn0 + tx * 8 + j;
            if (GUARD && col >= N) continue;
            size_t o = (size_t)row * ldc + col;
            float v = acc[i][j];
            if (EPI == EP_STORE) {
                C[o] = v;
            } else if (EPI == EP_ADD) {
                C[o] += v;
            } else if (EPI == EP_SUB) {
                C[o] -= v;
            } else if (EPI == EP_XHAT) {
                C[o] = dU[col] * (x0[(size_t)row * AD + col] + v);
            } else if (EPI == EP_XHAT_CLIP) {
                float xh = dU[col] * (x0[(size_t)row * AD + col] + v);
                C[o] = fminf(fmaxf(xh, mnv), mxv);
            } else {  // EP_ADMM / EP_ADMM_U0
                float uo = (EPI == EP_ADMM_U0) ? 0.0f : ubuf[o];
                float fxu = v + uo;
                float sa = fabsf(fxu) - 0.1f;  // LAMDA / RHO
                float z = sa > 0.0f ? copysignf(sa, fxu) : 0.0f;
                float un = uo + fxu - z;  // u + fxu - z  (reference formula)
                ubuf[o] = un;
                wbuf[o] = z - un;  // w = z_new - u_new
            }
        }
    }
}

// ---------------- launch ----------------
extern "C" void kernel_launch(void* const* d_in, const int* in_sizes, int n_in,
                              void* d_out, int out_size) {
    const float* y = (const float*)d_in[0];    // (B, M)
    const float* x = (const float*)d_in[1];    // (B, A)
    const float* a = (const float*)d_in[2];    // (M, A)
    const float* phi = (const float*)d_in[3];  // (S, A)
    float* out = (float*)d_out;                // (B, A)

    float *G, *linv, *dU, *x0, *xh, *u, *w;
    cudaGetSymbolAddress((void**)&G, g_G);
    cudaGetSymbolAddress((void**)&linv, g_linv);
    cudaGetSymbolAddress((void**)&dU, g_dU);
    cudaGetSymbolAddress((void**)&x0, g_x0);
    cudaGetSymbolAddress((void**)&xh, g_xh);
    cudaGetSymbolAddress((void**)&u, g_u);
    cudaGetSymbolAddress((void**)&w, g_w);

    dim3 blk(256);

    // min/max of x
    mm_init_k<<<1, 1>>>();
    mm_reduce_k<<<256, 256>>>(x, BD * AD);

    // G = a^T a + phi^T phi
    dim3 gAA(AD / 128, AD / 128);
    gemm_k<1, 0, EP_STORE, false><<<gAA, blk>>>(a, a, G, AD, AD, MD, AD, AD, AD,
                                                nullptr, nullptr, nullptr, nullptr);
    gemm_k<1, 0, EP_ADD, false><<<gAA, blk>>>(phi, phi, G, AD, AD, SD, AD, AD, AD,
                                              nullptr, nullptr, nullptr, nullptr);

    // blocked Cholesky -> dU
    for (int kb = 0; kb < AD / NB; kb++) {
        int k0 = kb * NB;
        chol_diag_k<<<1, NB>>>(G, linv, dU, k0);
        int nrem = AD - k0 - NB;
        if (nrem > 0) {
            panel_k<<<nrem / 32, 256>>>(G, linv, k0);
            dim3 gs((nrem + 127) / 128, (nrem + 127) / 128);
            float* Gp = G + (size_t)(k0 + NB) * AD + k0;
            float* Gc = G + (size_t)(k0 + NB) * AD + (k0 + NB);
            gemm_k<0, 1, EP_SUB, true><<<gs, blk>>>(Gp, Gp, Gc, nrem, nrem, NB, AD, AD, AD,
                                                    nullptr, nullptr, nullptr, nullptr);
        }
    }

    // x0 = y @ a
    gemm_k<0, 0, EP_STORE, false><<<gAA, blk>>>(y, a, x0, BD, AD, MD, MD, AD, AD,
                                                nullptr, nullptr, nullptr, nullptr);

    // iter 1: x_hat = dU * x0 (w = 0), then ADMM update with u = 0
    xhat1_k<<<(BD * AD) / 256, 256>>>(x0, dU, xh);
    dim3 g2(SD / 128, BD / 128);
    gemm_k<0, 1, EP_ADMM_U0, false><<<g2, blk>>>(xh, phi, nullptr, BD, SD, AD, AD, AD, SD,
                                                 nullptr, nullptr, u, w);

    // iters 2..9: full updates
    dim3 g1(AD / 128, BD / 128);
    for (int it = 2; it <= 9; it++) {
        gemm_k<0, 0, EP_XHAT, false><<<g1, blk>>>(w, phi, xh, BD, AD, SD, SD, AD, AD,
                                                  x0, dU, nullptr, nullptr);
        gemm_k<0, 1, EP_ADMM, false><<<g2, blk>>>(xh, phi, nullptr, BD, SD, AD, AD, AD, SD,
                                                  nullptr, nullptr, u, w);
    }

    // iter 10: only x_hat needed -> fused clip, write straight to d_out
    gemm_k<0, 0, EP_XHAT_CLIP, false><<<g1, blk>>>(w, phi, out, BD, AD, SD, SD, AD, AD,
                                                   x0, dU, nullptr, nullptr);
}

// round 4
// speedup vs baseline: 2.2452x; 2.2452x over previous
#include <cuda_runtime.h>
#include <cuda_bf16.h>
#include <cstdint>
#include <cstddef>

#define BD 2048
#define MD 512
#define AD 2048
#define SD 6144
#define NB 64

// smem stage layout: rows padded to 80B (32 bf16 + 16B pad) -> conflict-free lds
#define ROWB 80
#define OAL 10240
#define OBH 20480
#define OBL 30720
#define SSTG 40960
#define DSMEM_TOTAL (2 * SSTG)

__device__ float g_G[AD * AD];
__device__ float g_linv[NB * NB];
__device__ float g_dU[AD];
__device__ float g_x0[BD * AD];
__device__ float g_u[BD * SD];
__device__ unsigned g_mm[2];
__device__ __align__(16) __nv_bfloat16 g_phih[SD * AD], g_phil[SD * AD];
__device__ __align__(16) __nv_bfloat16 g_phiTh[AD * SD], g_phiTl[AD * SD];
__device__ __align__(16) __nv_bfloat16 g_aTh[AD * MD], g_aTl[AD * MD];
__device__ __align__(16) __nv_bfloat16 g_yh[BD * MD], g_yl[BD * MD];
__device__ __align__(16) __nv_bfloat16 g_wh[BD * SD], g_wl[BD * SD];
__device__ __align__(16) __nv_bfloat16 g_xhh[BD * AD], g_xhl[BD * AD];

__device__ __forceinline__ unsigned f2o(float f) {
    unsigned b = __float_as_uint(f);
    return (b & 0x80000000u) ? ~b : (b | 0x80000000u);
}
__device__ __forceinline__ float o2f(unsigned u) {
    unsigned b = (u & 0x80000000u) ? (u ^ 0x80000000u) : ~u;
    return __uint_as_float(b);
}
__device__ __forceinline__ void split_bf(float x, __nv_bfloat16& h, __nv_bfloat16& l) {
    __nv_bfloat16 hb = __float2bfloat16(x);
    h = hb;
    l = __float2bfloat16(x - __bfloat162float(hb));
}
__device__ __forceinline__ uint32_t s2u(const void* p) {
    uint32_t a;
    asm("{ .reg .u64 t; cvta.to.shared.u64 t, %1; cvt.u32.u64 %0, t; }" : "=r"(a) : "l"(p));
    return a;
}
__device__ __forceinline__ uint32_t lds32(uint32_t a) {
    uint32_t v;
    asm volatile("ld.shared.b32 %0, [%1];" : "=r"(v) : "r"(a));
    return v;
}
__device__ __forceinline__ void cp16(uint32_t d, const void* s) {
    asm volatile("cp.async.cg.shared.global [%0], [%1], 16;" ::"r"(d), "l"(s));
}
__device__ __forceinline__ void mma16816(float* c, const uint32_t* a, uint32_t b0, uint32_t b1) {
    asm volatile(
        "mma.sync.aligned.m16n8k16.row.col.f32.bf16.bf16.f32 "
        "{%0,%1,%2,%3}, {%4,%5,%6,%7}, {%8,%9}, {%0,%1,%2,%3};"
        : "+f"(c[0]), "+f"(c[1]), "+f"(c[2]), "+f"(c[3])
        : "r"(a[0]), "r"(a[1]), "r"(a[2]), "r"(a[3]), "r"(b0), "r"(b1));
}

__global__ void mm_init_k() {
    g_mm[0] = 0xFFFFFFFFu;
    g_mm[1] = 0u;
}
__global__ void mm_reduce_k(const float* __restrict__ x, int n) {
    unsigned mn = 0xFFFFFFFFu, mx = 0u;
    for (int i = blockIdx.x * blockDim.x + threadIdx.x; i < n; i += gridDim.x * blockDim.x) {
        unsigned o = f2o(x[i]);
        mn = min(mn, o);
        mx = max(mx, o);
    }
    __shared__ unsigned smn[256], smx[256];
    smn[threadIdx.x] = mn;
    smx[threadIdx.x] = mx;
    __syncthreads();
    for (int s = 128; s > 0; s >>= 1) {
        if (threadIdx.x < s) {
            smn[threadIdx.x] = min(smn[threadIdx.x], smn[threadIdx.x + s]);
            smx[threadIdx.x] = max(smx[threadIdx.x], smx[threadIdx.x + s]);
        }
        __syncthreads();
    }
    if (threadIdx.x == 0) {
        atomicMin(&g_mm[0], smn[0]);
        atomicMax(&g_mm[1], smx[0]);
    }
}

__global__ void split_k(const float* __restrict__ s, __nv_bfloat16* __restrict__ h,
                        __nv_bfloat16* __restrict__ l, int n) {
    int i = blockIdx.x * 256 + threadIdx.x;
    if (i < n) {
        __nv_bfloat16 hh, ll;
        split_bf(s[i], hh, ll);
        h[i] = hh;
        l[i] = ll;
    }
}

// out[c*R + r] = split(src[r*Cc + c])
__global__ void tsplit_k(const float* __restrict__ src, int R, int Cc,
                         __nv_bfloat16* __restrict__ th, __nv_bfloat16* __restrict__ tl) {
    __shared__ float t[32][33];
    int bc = blockIdx.x * 32, br = blockIdx.y * 32;
    int x = threadIdx.x, y = threadIdx.y;
#pragma unroll
    for (int dy = 0; dy < 32; dy += 8) t[y + dy][x] = src[(size_t)(br + y + dy) * Cc + bc + x];
    __syncthreads();
#pragma unroll
    for (int dy = 0; dy < 32; dy += 8) {
        size_t o = (size_t)(bc + y + dy) * R + br + x;
        __nv_bfloat16 h, l;
        split_bf(t[x][y + dy], h, l);
        th[o] = h;
        tl[o] = l;
    }
}

__global__ void chol_diag_k(float* __restrict__ G, float* __restrict__ linv,
                            float* __restrict__ dU, int k0) {
    __shared__ float s[NB][NB + 1];
    __shared__ float xs[NB][NB + 1];
    int tid = threadIdx.x;
    for (int j = 0; j < NB; j++) s[tid][j] = G[(size_t)(k0 + tid) * AD + k0 + j];
    __syncthreads();
    for (int j = 0; j < NB; j++) {
        float ajj = s[j][j];
        __syncthreads();
        float d = sqrtf(ajj);
        if (tid == j) {
            s[j][j] = d;
            dU[k0 + j] = 1.0f / (d * d);
        }
        if (tid > j) s[tid][j] /= d;
        __syncthreads();
        if (tid > j) {
            float lj = s[tid][j];
            for (int p = j + 1; p <= tid; p++) s[tid][p] -= lj * s[p][j];
        }
        __syncthreads();
    }
    int c = tid;
    for (int r = 0; r < c; r++) xs[r][c] = 0.0f;
    xs[c][c] = 1.0f / s[c][c];
    for (int r = c + 1; r < NB; r++) {
        float acc = 0.0f;
        for (int p = c; p < r; p++) acc += s[r][p] * xs[p][c];
        xs[r][c] = -acc / s[r][r];
    }
    for (int j = 0; j < NB; j++) linv[j * NB + c] = xs[j][c];
}

__global__ void panel_k(float* __restrict__ G, const float* __restrict__ linv, int k0) {
    __shared__ float li[NB][NB + 1];
    __shared__ float ar[32][NB];
    int tid = threadIdx.x;
    for (int i = tid; i < NB * NB; i += 256) li[i >> 6][i & 63] = linv[i];
    int row0 = k0 + NB + blockIdx.x * 32;
    for (int i = tid; i < 32 * NB; i += 256) {
        int r = i >> 6, p = i & 63;
        ar[r][p] = G[(size_t)(row0 + r) * AD + k0 + p];
    }
    __syncthreads();
    int j = tid & 63;
    for (int r = tid >> 6; r < 32; r += 4) {
        float acc = 0.0f;
#pragma unroll
        for (int p = 0; p < NB; p++) acc += ar[r][p] * li[j][p];
        G[(size_t)(row0 + r) * AD + k0 + j] = acc;
    }
}

// trailing update: C(Mr x Mr, ld) -= P(Mr x 64, ld) @ P^T
__global__ __launch_bounds__(256) void syrk_k(const float* __restrict__ P, float* __restrict__ C,
                                              int Mr, int ld) {
    __shared__ float As[16][128];
    __shared__ float Bs[16][128];
    int tid = threadIdx.x;
    int bm0 = blockIdx.y * 128, bn0 = blockIdx.x * 128;
    int tx = tid & 15, ty = tid >> 4;
    float acc[8][8];
#pragma unroll
    for (int i = 0; i < 8; i++)
#pragma unroll
        for (int j = 0; j < 8; j++) acc[i][j] = 0.0f;
    for (int k0 = 0; k0 < 64; k0 += 16) {
#pragma unroll
        for (int L = 0; L < 2; L++) {
            int idx = tid + L * 256;
            int r = idx >> 2, fk = (idx & 3) << 2;
            float4 v = make_float4(0.f, 0.f, 0.f, 0.f);
            if ((bm0 + r) < Mr) v = *(const float4*)(P + (size_t)(bm0 + r) * ld + k0 + fk);
            As[fk + 0][r] = v.x;
            As[fk + 1][r] = v.y;
            As[fk + 2][r] = v.z;
            As[fk + 3][r] = v.w;
        }
#pragma unroll
        for (int L = 0; L < 2; L++) {
            int idx = tid + L * 256;
            int r = idx >> 2, fk = (idx & 3) << 2;
            float4 v = make_float4(0.f, 0.f, 0.f, 0.f);
            if ((bn0 + r) < Mr) v = *(const float4*)(P + (size_t)(bn0 + r) * ld + k0 + fk);
            Bs[fk + 0][r] = v.x;
            Bs[fk + 1][r] = v.y;
            Bs[fk + 2][r] = v.z;
            Bs[fk + 3][r] = v.w;
        }
        __syncthreads();
#pragma unroll
        for (int k = 0; k < 16; k++) {
            float arf[8], brf[8];
#pragma unroll
            for (int i = 0; i < 8; i++) arf[i] = As[k][ty * 8 + i];
#pragma unroll
            for (int j = 0; j < 8; j++) brf[j] = Bs[k][tx * 8 + j];
#pragma unroll
            for (int i = 0; i < 8; i++)
#pragma unroll
                for (int j = 0; j < 8; j++) acc[i][j] += arf[i] * brf[j];
        }
        __syncthreads();
    }
#pragma unroll
    for (int i = 0; i < 8; i++) {
        int row = bm0 + ty * 8 + i;
        if (row >= Mr) continue;
#pragma unroll
        for (int j = 0; j < 8; j++) {
            int col = bn0 + tx * 8 + j;
            if (col >= Mr) continue;
            C[(size_t)row * ld + col] -= acc[i][j];
        }
    }
}

// ---------------- warp-MMA bf16x3 GEMM, fused epilogues ----------------
enum { EP_G_STORE = 0, EP_G_ADD, EP_X0, EP_XHAT, EP_XHAT_CLIP, EP_ADMM, EP_ADMM_U0 };

template <int EPI>
__device__ __forceinline__ void ep2(float2 v, int row, int col, int N, float* C,
                                    const float* x0p, const float* dUp, float* up,
                                    __nv_bfloat16* oh, __nv_bfloat16* ol, float* outp,
                                    float mnv, float mxv) {
    size_t o = (size_t)row * N + col;
    if (EPI == EP_G_STORE) {
        *(float2*)(C + o) = v;
    } else if (EPI == EP_G_ADD) {
        float2 g = *(float2*)(C + o);
        g.x += v.x;
        g.y += v.y;
        *(float2*)(C + o) = g;
    } else if (EPI == EP_X0) {
        *(float2*)(C + o) = v;
        float2 d = *(const float2*)(dUp + col);
        __nv_bfloat162 hh, ll;
        split_bf(d.x * v.x, hh.x, ll.x);
        split_bf(d.y * v.y, hh.y, ll.y);
        *(__nv_bfloat162*)(oh + o) = hh;
        *(__nv_bfloat162*)(ol + o) = ll;
    } else if (EPI == EP_XHAT) {
        float2 x0v = *(const float2*)(x0p + o);
        float2 d = *(const float2*)(dUp + col);
        __nv_bfloat162 hh, ll;
        split_bf(d.x * (x0v.x + v.x), hh.x, ll.x);
        split_bf(d.y * (x0v.y + v.y), hh.y, ll.y);
        *(__nv_bfloat162*)(oh + o) = hh;
        *(__nv_bfloat162*)(ol + o) = ll;
    } else if (EPI == EP_XHAT_CLIP) {
        float2 x0v = *(const float2*)(x0p + o);
        float2 d = *(const float2*)(dUp + col);
        float2 t;
        t.x = fminf(fmaxf(d.x * (x0v.x + v.x), mnv), mxv);
        t.y = fminf(fmaxf(d.y * (x0v.y + v.y), mnv), mxv);
        *(float2*)(outp + o) = t;
    } else {
        float2 uo = make_float2(0.f, 0.f);
        if (EPI == EP_ADMM) uo = *(float2*)(up + o);
        __nv_bfloat162 hh, ll;
        float2 un;
#pragma unroll
        for (int e = 0; e < 2; e++) {
            float fxu = (e ? v.y : v.x) + (e ? uo.y : uo.x);
            float sa = fabsf(fxu) - 0.1f;  // LAMDA / RHO
            float z = sa > 0.0f ? copysignf(sa, fxu) : 0.0f;
            float u2 = (e ? uo.y : uo.x) + fxu - z;
            if (e) un.y = u2; else un.x = u2;
            __nv_bfloat16 h, l;
            split_bf(z - u2, h, l);
            if (e) { hh.y = h; ll.y = l; } else { hh.x = h; ll.x = l; }
        }
        *(float2*)(up + o) = un;
        *(__nv_bfloat162*)(oh + o) = hh;
        *(__nv_bfloat162*)(ol + o) = ll;
    }
}

template <int EPI>
__global__ __launch_bounds__(256, 2) void tgemm_k(
    const __nv_bfloat16* __restrict__ Ah, const __nv_bfloat16* __restrict__ Al, int lda,
    const __nv_bfloat16* __restrict__ Bh, const __nv_bfloat16* __restrict__ Bl, int ldb,
    int K, int N, float* __restrict__ C, const float* __restrict__ x0p,
    const float* __restrict__ dUp, float* __restrict__ up, __nv_bfloat16* __restrict__ oh,
    __nv_bfloat16* __restrict__ ol, float* __restrict__ outp) {
    extern __shared__ char ds[];
    uint32_t sb = s2u(ds);
    int tid = threadIdx.x, wid = tid >> 5, lane = tid & 31;
    int q = lane >> 2, t = lane & 3;
    int wm = wid >> 1, wn = wid & 1;
    int m0 = blockIdx.y * 128, n0 = blockIdx.x * 128;

    float acc[2][8][4];
#pragma unroll
    for (int mi = 0; mi < 2; mi++)
#pragma unroll
        for (int nj = 0; nj < 8; nj++)
#pragma unroll
            for (int e = 0; e < 4; e++) acc[mi][nj][e] = 0.0f;

    int lr = tid >> 2, lc = tid & 3;  // load row (0..63), chunk (0..3)
    int nK = K / 32;

    // ---- issue stage 0 ----
    {
        uint32_t st = sb;
        int gc = lc * 8;
#pragma unroll
        for (int i = 0; i < 2; i++) {
            int r = lr + i * 64;
            uint32_t dso = st + r * ROWB + lc * 16;
            cp16(dso, Ah + (size_t)(m0 + r) * lda + gc);
            cp16(dso + OAL, Al + (size_t)(m0 + r) * lda + gc);
            cp16(dso + OBH, Bh + (size_t)(n0 + r) * ldb + gc);
            cp16(dso + OBL, Bl + (size_t)(n0 + r) * ldb + gc);
        }
        asm volatile("cp.async.commit_group;" ::: "memory");
    }

    for (int kb = 0; kb < nK; kb++) {
        int buf = kb & 1;
        if (kb + 1 < nK) {
            uint32_t st = sb + (buf ^ 1) * SSTG;
            int gc = (kb + 1) * 32 + lc * 8;
#pragma unroll
            for (int i = 0; i < 2; i++) {
                int r = lr + i * 64;
                uint32_t dso = st + r * ROWB + lc * 16;
                cp16(dso, Ah + (size_t)(m0 + r) * lda + gc);
                cp16(dso + OAL, Al + (size_t)(m0 + r) * lda + gc);
                cp16(dso + OBH, Bh + (size_t)(n0 + r) * ldb + gc);
                cp16(dso + OBL, Bl + (size_t)(n0 + r) * ldb + gc);
            }
            asm volatile("cp.async.commit_group;" ::: "memory");
            asm volatile("cp.async.wait_group 1;" ::: "memory");
        } else {
            asm volatile("cp.async.wait_group 0;" ::: "memory");
        }
        __syncthreads();

        uint32_t st = sb + buf * SSTG;
        uint32_t abase = st + (wm * 32 + q) * ROWB + t * 4;
        uint32_t bbase = st + OBH + (wn * 64 + q) * ROWB + t * 4;
#pragma unroll
        for (int s = 0; s < 2; s++) {
            uint32_t ko = s * 32;
            uint32_t ah[2][4], al[2][4];
#pragma unroll
            for (int mi = 0; mi < 2; mi++) {
                uint32_t ro = abase + mi * (16 * ROWB) + ko;
                ah[mi][0] = lds32(ro);
                ah[mi][1] = lds32(ro + 8 * ROWB);
                ah[mi][2] = lds32(ro + 16);
                ah[mi][3] = lds32(ro + 8 * ROWB + 16);
                al[mi][0] = lds32(ro + OAL);
                al[mi][1] = lds32(ro + OAL + 8 * ROWB);
                al[mi][2] = lds32(ro + OAL + 16);
                al[mi][3] = lds32(ro + OAL + 8 * ROWB + 16);
            }
#pragma unroll
            for (int nj = 0; nj < 8; nj++) {
                uint32_t bo = bbase + nj * (8 * ROWB) + ko;
                uint32_t bh0 = lds32(bo), bh1 = lds32(bo + 16);
                uint32_t bl0 = lds32(bo + 10240), bl1 = lds32(bo + 10240 + 16);
#pragma unroll
                for (int mi = 0; mi < 2; mi++) {
                    mma16816(acc[mi][nj], ah[mi], bh0, bh1);
                    mma16816(acc[mi][nj], ah[mi], bl0, bl1);
                    mma16816(acc[mi][nj], al[mi], bh0, bh1);
                }
            }
        }
        __syncthreads();
    }

    float mnv = 0.f, mxv = 0.f;
    if (EPI == EP_XHAT_CLIP) {
        mnv = o2f(g_mm[0]);
        mxv = o2f(g_mm[1]);
    }
#pragma unroll
    for (int mi = 0; mi < 2; mi++)
#pragma unroll
        for (int nj = 0; nj < 8; nj++) {
            int row = m0 + wm * 32 + mi * 16 + q;
            int col = n0 + wn * 64 + nj * 8 + 2 * t;
            ep2<EPI>(make_float2(acc[mi][nj][0], acc[mi][nj][1]), row, col, N, C, x0p, dUp, up,
                     oh, ol, outp, mnv, mxv);
            ep2<EPI>(make_float2(acc[mi][nj][2], acc[mi][nj][3]), row + 8, col, N, C, x0p, dUp,
                     up, oh, ol, outp, mnv, mxv);
        }
}

extern "C" void kernel_launch(void* const* d_in, const int* in_sizes, int n_in,
                              void* d_out, int out_size) {
    const float* y = (const float*)d_in[0];
    const float* x = (const float*)d_in[1];
    const float* a = (const float*)d_in[2];
    const float* phi = (const float*)d_in[3];
    float* out = (float*)d_out;

    float *G, *linv, *dU, *x0, *u;
    __nv_bfloat16 *phih, *phil, *phiTh, *phiTl, *aTh, *aTl, *yh, *yl, *wh, *wl, *xhh, *xhl;
    cudaGetSymbolAddress((void**)&G, g_G);
    cudaGetSymbolAddress((void**)&linv, g_linv);
    cudaGetSymbolAddress((void**)&dU, g_dU);
    cudaGetSymbolAddress((void**)&x0, g_x0);
    cudaGetSymbolAddress((void**)&u, g_u);
    cudaGetSymbolAddress((void**)&phih, g_phih);
    cudaGetSymbolAddress((void**)&phil, g_phil);
    cudaGetSymbolAddress((void**)&phiTh, g_phiTh);
    cudaGetSymbolAddress((void**)&phiTl, g_phiTl);
    cudaGetSymbolAddress((void**)&aTh, g_aTh);
    cudaGetSymbolAddress((void**)&aTl, g_aTl);
    cudaGetSymbolAddress((void**)&yh, g_yh);
    cudaGetSymbolAddress((void**)&yl, g_yl);
    cudaGetSymbolAddress((void**)&wh, g_wh);
    cudaGetSymbolAddress((void**)&wl, g_wl);
    cudaGetSymbolAddress((void**)&xhh, g_xhh);
    cudaGetSymbolAddress((void**)&xhl, g_xhl);

    cudaFuncSetAttribute(tgemm_k<EP_G_STORE>, cudaFuncAttributeMaxDynamicSharedMemorySize, DSMEM_TOTAL);
    cudaFuncSetAttribute(tgemm_k<EP_G_ADD>, cudaFuncAttributeMaxDynamicSharedMemorySize, DSMEM_TOTAL);
    cudaFuncSetAttribute(tgemm_k<EP_X0>, cudaFuncAttributeMaxDynamicSharedMemorySize, DSMEM_TOTAL);
    cudaFuncSetAttribute(tgemm_k<EP_XHAT>, cudaFuncAttributeMaxDynamicSharedMemorySize, DSMEM_TOTAL);
    cudaFuncSetAttribute(tgemm_k<EP_XHAT_CLIP>, cudaFuncAttributeMaxDynamicSharedMemorySize, DSMEM_TOTAL);
    cudaFuncSetAttribute(tgemm_k<EP_ADMM>, cudaFuncAttributeMaxDynamicSharedMemorySize, DSMEM_TOTAL);
    cudaFuncSetAttribute(tgemm_k<EP_ADMM_U0>, cudaFuncAttributeMaxDynamicSharedMemorySize, DSMEM_TOTAL);

    mm_init_k<<<1, 1>>>();
    mm_reduce_k<<<256, 256>>>(x, BD * AD);

    split_k<<<(SD * AD) / 256, 256>>>(phi, phih, phil, SD * AD);
    split_k<<<(BD * MD) / 256, 256>>>(y, yh, yl, BD * MD);
    {
        dim3 b(32, 8);
        tsplit_k<<<dim3(AD / 32, SD / 32), b>>>(phi, SD, AD, phiTh, phiTl);
        tsplit_k<<<dim3(AD / 32, MD / 32), b>>>(a, MD, AD, aTh, aTl);
    }

    dim3 blk(256);
    dim3 gG(AD / 128, AD / 128);
    tgemm_k<EP_G_STORE><<<gG, blk, DSMEM_TOTAL>>>(aTh, aTl, MD, aTh, aTl, MD, MD, AD, G,
                                                  nullptr, nullptr, nullptr, nullptr, nullptr, nullptr);
    tgemm_k<EP_G_ADD><<<gG, blk, DSMEM_TOTAL>>>(phiTh, phiTl, SD, phiTh, phiTl, SD, SD, AD, G,
                                                nullptr, nullptr, nullptr, nullptr, nullptr, nullptr);

    for (int kb = 0; kb < AD / NB; kb++) {
        int k0 = kb * NB;
        chol_diag_k<<<1, NB>>>(G, linv, dU, k0);
        int nrem = AD - k0 - NB;
        if (nrem > 0) {
            panel_k<<<nrem / 32, 256>>>(G, linv, k0);
            dim3 gs((nrem + 127) / 128, (nrem + 127) / 128);
            float* Gp = G + (size_t)(k0 + NB) * AD + k0;
            float* Gc = G + (size_t)(k0 + NB) * AD + (k0 + NB);
            syrk_k<<<gs, blk>>>(Gp, Gc, nrem, AD);
        }
    }

    dim3 g1(AD / 128, BD / 128);  // C is (B, A)
    dim3 g2(SD / 128, BD / 128);  // C is (B, S)

    // x0 = y@a ; also xh = dU*x0 (iter-1, w=0)
    tgemm_k<EP_X0><<<g1, blk, DSMEM_TOTAL>>>(yh, yl, MD, aTh, aTl, MD, MD, AD, x0,
                                             nullptr, dU, nullptr, xhh, xhl, nullptr);
    // iter 1 second half: u = 0
    tgemm_k<EP_ADMM_U0><<<g2, blk, DSMEM_TOTAL>>>(xhh, xhl, AD, phih, phil, AD, AD, SD, nullptr,
                                                  nullptr, nullptr, u, wh, wl, nullptr);
    for (int it = 2; it <= 9; it++) {
        tgemm_k<EP_XHAT><<<g1, blk, DSMEM_TOTAL>>>(wh, wl, SD, phiTh, phiTl, SD, SD, AD, nullptr,
                                                   x0, dU, nullptr, xhh, xhl, nullptr);
        tgemm_k<EP_ADMM><<<g2, blk, DSMEM_TOTAL>>>(xhh, xhl, AD, phih, phil, AD, AD, SD, nullptr,
                                                   nullptr, nullptr, u, wh, wl, nullptr);
    }
    tgemm_k<EP_XHAT_CLIP><<<g1, blk, DSMEM_TOTAL>>>(wh, wl, SD, phiTh, phiTl, SD, SD, AD, nullptr,
                                                    x0, dU, nullptr, nullptr, nullptr, out);
}